// round 11
// baseline (speedup 1.0000x reference)
#include <cuda_runtime.h>
#include <cuda_fp16.h>
#include <cstdint>

#define BATCH 8
#define NSEQ  4096
#define DD    512
#define MROWS (BATCH * NSEQ)   // 32768

// ---------------- scratch (__device__ globals; allocation-free rule) -------
__device__ __half g_aH[MROWS * DD], g_aL[MROWS * DD];   // split of a
__device__ __half g_bH[MROWS * DD], g_bL[MROWS * DD];   // split of b
__device__ __half g_kH[MROWS * DD], g_kL[MROWS * DD];   // split of normalized K
__device__ __half g_tH[MROWS * DD], g_tL[MROWS * DD];   // split of T
__device__ __half g_WHq[DD * DD], g_WHk[DD * DD], g_WHf[DD * DD];
__device__ __half g_WpB[BATCH][DD * DD];                // fp16(Wp * diag(G[b]))
__device__ float g_Q[MROWS * DD];
__device__ float g_K[MROWS * DD];
__device__ float g_A[MROWS];
__device__ float g_invA[BATCH];
__device__ float g_G[BATCH * DD];
__device__ float g_Gp[8][BATCH * DD];

__device__ __forceinline__ uint32_t s2u(const void* p) {
    uint32_t a;
    asm("{ .reg .u64 t; cvta.to.shared.u64 t, %1; cvt.u32.u64 %0, t; }"
        : "=r"(a) : "l"(p));
    return a;
}
__device__ __forceinline__ unsigned short us(__half h) {
    return __half_as_ushort(h);
}
__device__ __forceinline__ uint32_t pk(__half a, __half b) {
    return (uint32_t)us(a) | ((uint32_t)us(b) << 16);
}

#define MMA_F16(d, a, b)                                                     \
    asm volatile(                                                            \
        "mma.sync.aligned.m16n8k16.row.col.f32.f16.f16.f32 "                 \
        "{%0,%1,%2,%3},{%4,%5,%6,%7},{%8,%9},{%0,%1,%2,%3};"                 \
        : "+f"(d[0]), "+f"(d[1]), "+f"(d[2]), "+f"(d[3])                     \
        : "r"(a[0]), "r"(a[1]), "r"(a[2]), "r"(a[3]), "r"(b[0]), "r"(b[1]))

#define CP16(dst, src)                                                       \
    asm volatile("cp.async.ca.shared.global [%0], [%1], 16;"                 \
                 :: "r"(dst), "l"(src))
#define CP_COMMIT() asm volatile("cp.async.commit_group;" ::: "memory")
#define CP_WAIT2()  asm volatile("cp.async.wait_group 2;" ::: "memory")

// ---------------- tensor-core GEMM: 2-term fp16 split ----------------------
// C[m,n] = sum_k A[m,k]*W[n,k], A = Ah+Al (fp16 pair), W = Wh (fp16).
// Block 128x128, BK=32 (2 x 16-k subtiles), 8 warps (4m x 2n), warp 32x64.
// smem/stage: 3 planes (Ah, Al, Wh), each 2 subtiles x 128 rows x 24 halves
// (16 data + 8 pad -> 12-word stride, conflict-free). 3-stage cp.async pipe.
// MMA schedule: all 16 independent hh-MMAs, then all 16 lh-MMAs -> same-
// accumulator reuse distance 16 (hides HMMA latency; R10 had distance 1).
constexpr int SUB_B   = 128 * 48;          // 6144 B per 16-k subtile plane
constexpr int PLANE_B = 2 * SUB_B;         // 12288
constexpr int STAGE_B = 3 * PLANE_B;       // 36864
constexpr int HDR     = 2048;
constexpr int SMEM_TOTAL = HDR + 3 * STAGE_B;   // 112640 B
constexpr int NSTG = 16;                   // K = 512 / 32

// CFG: 0: A=a,   W=WHq,        out fp32 g_Q  (+bq)
//      1: A=b,   W=WHk,        out fp32 g_K  (+bk)
//      2: A=K,   W=WpB[batch], out split g_tH/L (+bp + g_Q residual)
//      3: A=T,   W=WHf,        out fp32 outf (+bf)
template<int CFG>
__global__ __launch_bounds__(256)
void gemm7(const float* __restrict__ bias, float* __restrict__ outf)
{
    const int m0 = blockIdx.y * 128, n0 = blockIdx.x * 128;
    const __half* Ah_ = (CFG == 0) ? g_aH : (CFG == 1) ? g_bH : (CFG == 2) ? g_kH : g_tH;
    const __half* Al_ = (CFG == 0) ? g_aL : (CFG == 1) ? g_bL : (CFG == 2) ? g_kL : g_tL;
    const __half* Wh_ = (CFG == 0) ? g_WHq : (CFG == 1) ? g_WHk
                       : (CFG == 2) ? g_WpB[m0 >> 12] : g_WHf;

    extern __shared__ char smem[];
    const int t = threadIdx.x, lane = t & 31, w = t >> 5;
    const int wm = (w >> 1) * 32, wn = (w & 1) * 64;
    const int g = lane >> 2, tg = lane & 3;

    if (t < 128) ((float*)smem)[t] = bias[n0 + t];

    const uint32_t sbase = s2u(smem) + HDR;

    auto fill = [&](int s, int buf) {
        uint32_t bp = sbase + buf * STAGE_B;
        #pragma unroll
        for (int i = 0; i < 6; i++) {
            const int plane = i >> 1;
            const int p = (i & 1) * 256 + t;
            const int row = p >> 2, sub = (p >> 1) & 1, cc = p & 1;
            const __half* gp = (plane == 0) ? Ah_ : (plane == 1) ? Al_ : Wh_;
            const int rbase = (plane < 2) ? m0 : n0;
            const void* src = gp + (rbase + row) * DD + s * 32 + sub * 16 + cc * 8;
            uint32_t dst = bp + plane * PLANE_B + sub * SUB_B + row * 48 + cc * 16;
            CP16(dst, src);
        }
    };

    float c[2][8][4] = {};

    fill(0, 0); CP_COMMIT();
    fill(1, 1); CP_COMMIT();

    for (int s = 0; s < NSTG; s++) {
        if (s + 2 < NSTG) fill(s + 2, (s + 2) % 3);
        CP_COMMIT();
        CP_WAIT2();
        __syncthreads();

        const uint32_t* base = (const uint32_t*)(smem + HDR + (s % 3) * STAGE_B);
        #pragma unroll
        for (int kk = 0; kk < 2; kk++) {
            const uint32_t* Awh = base + kk * (SUB_B / 4);
            const uint32_t* Awl = Awh + PLANE_B / 4;
            const uint32_t* Bwh = Awh + 2 * (PLANE_B / 4);

            uint32_t ah[2][4], al[2][4];
            #pragma unroll
            for (int i = 0; i < 2; i++) {
                int r = wm + i * 16 + g;
                ah[i][0] = Awh[r * 12 + tg];
                ah[i][1] = Awh[(r + 8) * 12 + tg];
                ah[i][2] = Awh[r * 12 + tg + 4];
                ah[i][3] = Awh[(r + 8) * 12 + tg + 4];
                al[i][0] = Awl[r * 12 + tg];
                al[i][1] = Awl[(r + 8) * 12 + tg];
                al[i][2] = Awl[r * 12 + tg + 4];
                al[i][3] = Awl[(r + 8) * 12 + tg + 4];
            }
            uint32_t bh[8][2];
            #pragma unroll
            for (int j = 0; j < 8; j++) {
                int nb = wn + j * 8 + g;
                bh[j][0] = Bwh[nb * 12 + tg];
                bh[j][1] = Bwh[nb * 12 + tg + 4];
            }
            // Pass 1: 16 independent hh MMAs
            #pragma unroll
            for (int i = 0; i < 2; i++)
                #pragma unroll
                for (int j = 0; j < 8; j++)
                    MMA_F16(c[i][j], ah[i], bh[j]);
            // Pass 2: 16 independent lh MMAs (RAW distance 16 to pass 1)
            #pragma unroll
            for (int i = 0; i < 2; i++)
                #pragma unroll
                for (int j = 0; j < 8; j++)
                    MMA_F16(c[i][j], al[i], bh[j]);
        }
        __syncthreads();
    }

    // Epilogue
    const float* sbias = (const float*)smem;
    #pragma unroll
    for (int i = 0; i < 2; i++) {
        #pragma unroll
        for (int j = 0; j < 8; j++) {
            int rm = m0 + wm + i * 16 + g;
            int cn = n0 + wn + j * 8 + 2 * tg;
            float2 bb = *(const float2*)&sbias[cn - n0];
            float v00 = c[i][j][0] + bb.x, v01 = c[i][j][1] + bb.y;
            float v10 = c[i][j][2] + bb.x, v11 = c[i][j][3] + bb.y;
            if (CFG != 2) {
                float* Cp = (CFG == 0) ? g_Q : (CFG == 1) ? g_K : outf;
                *(float2*)&Cp[rm * DD + cn]       = make_float2(v00, v01);
                *(float2*)&Cp[(rm + 8) * DD + cn] = make_float2(v10, v11);
            } else {
                float2 r0 = *(const float2*)&g_Q[rm * DD + cn];
                float2 r1 = *(const float2*)&g_Q[(rm + 8) * DD + cn];
                v00 += r0.x; v01 += r0.y; v10 += r1.x; v11 += r1.y;
                __half h00 = __float2half_rn(v00), h01 = __float2half_rn(v01);
                __half h10 = __float2half_rn(v10), h11 = __float2half_rn(v11);
                *(uint32_t*)&g_tH[rm * DD + cn]       = pk(h00, h01);
                *(uint32_t*)&g_tH[(rm + 8) * DD + cn] = pk(h10, h11);
                __half l00 = __float2half_rn(v00 - __half2float(h00));
                __half l01 = __float2half_rn(v01 - __half2float(h01));
                __half l10 = __float2half_rn(v10 - __half2float(h10));
                __half l11 = __float2half_rn(v11 - __half2float(h11));
                *(uint32_t*)&g_tL[rm * DD + cn]       = pk(l00, l01);
                *(uint32_t*)&g_tL[(rm + 8) * DD + cn] = pk(l10, l11);
            }
        }
    }
}

// ---------------- preprocessing kernels ------------------------------------
// hi/lo fp16 split of inputs a (DST=0) and b (DST=1)
template<int DST>
__global__ __launch_bounds__(256)
void splitin(const float4* __restrict__ src)
{
    __half* hp = (DST == 0) ? g_aH : g_bH;
    __half* lp = (DST == 0) ? g_aL : g_bL;
    int i = blockIdx.x * 256 + threadIdx.x;
    float4 v = src[i];
    __half h0 = __float2half_rn(v.x), h1 = __float2half_rn(v.y);
    __half h2 = __float2half_rn(v.z), h3 = __float2half_rn(v.w);
    __half l0 = __float2half_rn(v.x - __half2float(h0));
    __half l1 = __float2half_rn(v.y - __half2float(h1));
    __half l2 = __float2half_rn(v.z - __half2float(h2));
    __half l3 = __float2half_rn(v.w - __half2float(h3));
    ((uint2*)hp)[i] = make_uint2(pk(h0, h1), pk(h2, h3));
    ((uint2*)lp)[i] = make_uint2(pk(l0, l1), pk(l2, l3));
}

// fp16 round of a weight matrix. WI selects the DEVICE-side destination —
// device globals must never be passed as host-side kernel arguments.
template<int WI>
__global__ __launch_bounds__(256)
void roundw(const float4* __restrict__ src)
{
    __half* dst = (WI == 0) ? g_WHq : (WI == 1) ? g_WHk : g_WHf;
    int i = blockIdx.x * 256 + threadIdx.x;
    float4 v = src[i];
    ((uint2*)dst)[i] = make_uint2(pk(__float2half_rn(v.x), __float2half_rn(v.y)),
                                  pk(__float2half_rn(v.z), __float2half_rn(v.w)));
}

// WpB[b] = fp16(Wp * diag(G[b])) ; grid (DD*DD/1024, BATCH), block 256
__global__ __launch_bounds__(256)
void wpscale(const float4* __restrict__ Wp)
{
    int b = blockIdx.y;
    int i = blockIdx.x * 256 + threadIdx.x;   // float4 index
    int d = (i * 4) & (DD - 1);
    float4 v = Wp[i];
    float4 gv = *(const float4*)&g_G[b * DD + d];
    ((uint2*)g_WpB[b])[i] =
        make_uint2(pk(__float2half_rn(v.x * gv.x), __float2half_rn(v.y * gv.y)),
                   pk(__float2half_rn(v.z * gv.z), __float2half_rn(v.w * gv.w)));
}

// ---------------- l2norm + score + K split ---------------------------------
__global__ __launch_bounds__(128)
void l2norm_ascore(const float* __restrict__ wg)
{
    int rowg = blockIdx.x;
    bool isQ = rowg < MROWS;
    int r = isQ ? rowg : rowg - MROWS;
    const float* X = isQ ? g_Q : g_K;

    float4 v = *((const float4*)&X[r * DD] + threadIdx.x);
    float s = v.x * v.x + v.y * v.y + v.z * v.z + v.w * v.w;
    #pragma unroll
    for (int off = 16; off > 0; off >>= 1)
        s += __shfl_xor_sync(0xFFFFFFFFu, s, off);

    __shared__ float ws[4];
    int lane = threadIdx.x & 31, wid = threadIdx.x >> 5;
    if (lane == 0) ws[wid] = s;
    __syncthreads();
    float tot = ws[0] + ws[1] + ws[2] + ws[3];
    float inv = 1.0f / fmaxf(sqrtf(tot), 1e-12f);

    v.x *= inv; v.y *= inv; v.z *= inv; v.w *= inv;

    if (isQ) {
        *((float4*)&g_Q[r * DD] + threadIdx.x) = v;
        const float4* wv = reinterpret_cast<const float4*>(wg);
        float4 wq = wv[threadIdx.x];
        float s2 = v.x * wq.x + v.y * wq.y + v.z * wq.z + v.w * wq.w;
        #pragma unroll
        for (int off = 16; off > 0; off >>= 1)
            s2 += __shfl_xor_sync(0xFFFFFFFFu, s2, off);
        __syncthreads();
        if (lane == 0) ws[wid] = s2;
        __syncthreads();
        if (threadIdx.x == 0)
            g_A[r] = (ws[0] + ws[1] + ws[2] + ws[3]) * 4.419417382415922e-2f;
    } else {
        __half h0 = __float2half_rn(v.x), h1 = __float2half_rn(v.y);
        __half h2 = __float2half_rn(v.z), h3 = __float2half_rn(v.w);
        __half l0 = __float2half_rn(v.x - __half2float(h0));
        __half l1 = __float2half_rn(v.y - __half2float(h1));
        __half l2 = __float2half_rn(v.z - __half2float(h2));
        __half l3 = __float2half_rn(v.w - __half2float(h3));
        int o = r * DD + threadIdx.x * 4;
        *(uint2*)&g_kH[o] = make_uint2(pk(h0, h1), pk(h2, h3));
        *(uint2*)&g_kL[o] = make_uint2(pk(l0, l1), pk(l2, l3));
    }
}

__global__ __launch_bounds__(256)
void norma()
{
    int b = blockIdx.x, t = threadIdx.x;
    float s = 0.0f;
    for (int i = t; i < NSEQ; i += 256) {
        float v = g_A[b * NSEQ + i];
        s += v * v;
    }
    #pragma unroll
    for (int off = 16; off > 0; off >>= 1)
        s += __shfl_xor_sync(0xFFFFFFFFu, s, off);
    __shared__ float ws[8];
    int lane = t & 31, wid = t >> 5;
    if (lane == 0) ws[wid] = s;
    __syncthreads();
    if (t == 0) {
        float tot = 0.0f;
        #pragma unroll
        for (int i = 0; i < 8; i++) tot += ws[i];
        g_invA[b] = 1.0f / fmaxf(sqrtf(tot), 1e-12f);
    }
}

__global__ __launch_bounds__(128)
void gpoolp()
{
    int b = blockIdx.y;
    int d = blockIdx.x * 128 + threadIdx.x;
    int ns = blockIdx.z;
    int n0 = ns * (NSEQ / 8);
    float acc = 0.0f;
    #pragma unroll 4
    for (int n = n0; n < n0 + NSEQ / 8; n++)
        acc += g_A[b * NSEQ + n] * g_Q[(b * NSEQ + n) * DD + d];
    g_Gp[ns][b * DD + d] = acc;
}

__global__ __launch_bounds__(128)
void gpoolr()
{
    int i = blockIdx.x * 128 + threadIdx.x;
    int b = i / DD;
    float s = 0.0f;
    #pragma unroll
    for (int p = 0; p < 8; p++) s += g_Gp[p][i];
    g_G[i] = s * g_invA[b];
}

// ---------------------------------------------------------------------------
extern "C" void kernel_launch(void* const* d_in, const int* in_sizes, int n_in,
                              void* d_out, int out_size)
{
    const float* a  = (const float*)d_in[0];
    const float* b  = (const float*)d_in[1];
    const float* Wq = (const float*)d_in[2];
    const float* bq = (const float*)d_in[3];
    const float* Wk = (const float*)d_in[4];
    const float* bk = (const float*)d_in[5];
    const float* wg = (const float*)d_in[6];
    const float* Wp = (const float*)d_in[7];
    const float* bp = (const float*)d_in[8];
    const float* Wf = (const float*)d_in[9];
    const float* bf = (const float*)d_in[10];
    float* out = (float*)d_out;

    cudaFuncSetAttribute(gemm7<0>, cudaFuncAttributeMaxDynamicSharedMemorySize, SMEM_TOTAL);
    cudaFuncSetAttribute(gemm7<1>, cudaFuncAttributeMaxDynamicSharedMemorySize, SMEM_TOTAL);
    cudaFuncSetAttribute(gemm7<2>, cudaFuncAttributeMaxDynamicSharedMemorySize, SMEM_TOTAL);
    cudaFuncSetAttribute(gemm7<3>, cudaFuncAttributeMaxDynamicSharedMemorySize, SMEM_TOTAL);

    const int IN4 = MROWS * DD / 4;   // input float4 count
    const int W4  = DD * DD / 4;      // weight float4 count

    splitin<0><<<IN4 / 256, 256>>>((const float4*)a);
    splitin<1><<<IN4 / 256, 256>>>((const float4*)b);
    roundw<0><<<W4 / 256, 256>>>((const float4*)Wq);
    roundw<1><<<W4 / 256, 256>>>((const float4*)Wk);
    roundw<2><<<W4 / 256, 256>>>((const float4*)Wf);

    dim3 gg(4, MROWS / 128);   // (4, 256)

    gemm7<0><<<gg, 256, SMEM_TOTAL>>>(bq, nullptr);   // Q = a@Wq^T + bq
    gemm7<1><<<gg, 256, SMEM_TOTAL>>>(bk, nullptr);   // K = b@Wk^T + bk
    l2norm_ascore<<<2 * MROWS, 128>>>(wg);
    norma<<<BATCH, 256>>>();
    gpoolp<<<dim3(4, BATCH, 8), 128>>>();
    gpoolr<<<32, 128>>>();
    wpscale<<<dim3(W4 / 256, BATCH), 256>>>((const float4*)Wp);
    gemm7<2><<<gg, 256, SMEM_TOTAL>>>(bp, nullptr);   // T = K@(Wp*G)^T+bp+Q (split)
    gemm7<3><<<gg, 256, SMEM_TOTAL>>>(bf, out);       // out = T@Wf^T + bf
}

// round 13
// speedup vs baseline: 1.5738x; 1.5738x over previous
#include <cuda_runtime.h>
#include <cuda_fp16.h>
#include <cstdint>

#define BATCH 8
#define NSEQ  4096
#define DD    512
#define MROWS (BATCH * NSEQ)   // 32768

// ---------------- scratch (__device__ globals; allocation-free rule) -------
__device__ __half g_aH[MROWS * DD];        // fp16(a)
__device__ __half g_bH[MROWS * DD];        // fp16(b)
__device__ __half g_kH[MROWS * DD];        // fp16(normalized K)
__device__ __half g_tH[MROWS * DD];        // fp16(T)
__device__ __half g_WHq[DD * DD], g_WHk[DD * DD], g_WHf[DD * DD];
__device__ __half g_WpB[BATCH][DD * DD];   // fp16(Wp * diag(G[b]))
__device__ float g_Q[MROWS * DD];
__device__ float g_K[MROWS * DD];
__device__ float g_A[MROWS];
__device__ float g_invA[BATCH];
__device__ float g_G[BATCH * DD];
__device__ float g_Gp[8][BATCH * DD];

__device__ __forceinline__ uint32_t s2u(const void* p) {
    uint32_t a;
    asm("{ .reg .u64 t; cvta.to.shared.u64 t, %1; cvt.u32.u64 %0, t; }"
        : "=r"(a) : "l"(p));
    return a;
}
__device__ __forceinline__ unsigned short us(__half h) {
    return __half_as_ushort(h);
}
__device__ __forceinline__ uint32_t pk(__half a, __half b) {
    return (uint32_t)us(a) | ((uint32_t)us(b) << 16);
}

#define MMA_F16(d, a, b)                                                     \
    asm volatile(                                                            \
        "mma.sync.aligned.m16n8k16.row.col.f32.f16.f16.f32 "                 \
        "{%0,%1,%2,%3},{%4,%5,%6,%7},{%8,%9},{%0,%1,%2,%3};"                 \
        : "+f"(d[0]), "+f"(d[1]), "+f"(d[2]), "+f"(d[3])                     \
        : "r"(a[0]), "r"(a[1]), "r"(a[2]), "r"(a[3]), "r"(b[0]), "r"(b[1]))

#define CP16(dst, src)                                                       \
    asm volatile("cp.async.ca.shared.global [%0], [%1], 16;"                 \
                 :: "r"(dst), "l"(src))
#define CP_COMMIT() asm volatile("cp.async.commit_group;" ::: "memory")
#define CP_WAIT2()  asm volatile("cp.async.wait_group 2;" ::: "memory")

// ---------------- tensor-core GEMM: plain fp16 (1 term) --------------------
// C[m,n] = sum_k A[m,k]*W[n,k] + bias (+residual). A, W pre-rounded fp16.
// Block 128x128, BK=32 (2 x 16-k subtiles), 8 warps (4m x 2n), warp 32x64.
// smem/stage: 2 planes (A, W), each 2 subtiles x 128 rows x 24 halves
// (16 data + 8 pad -> 12-word stride, conflict-free). 3-stage cp.async pipe.
constexpr int SUB_B   = 128 * 48;          // 6144 B per 16-k subtile plane
constexpr int PLANE_B = 2 * SUB_B;         // 12288
constexpr int STAGE_B = 2 * PLANE_B;       // 24576
constexpr int HDR     = 2048;
constexpr int SMEM_TOTAL = HDR + 3 * STAGE_B;   // 75776 B
constexpr int NSTG = 16;                   // K = 512 / 32

// CFG: 0: A=g_aH, W=WHq,        out fp32 g_Q  (+bq)
//      1: A=g_bH, W=WHk,        out fp32 g_K  (+bk)
//      2: A=g_kH, W=WpB[batch], out fp16 g_tH (+bp + g_Q residual)
//      3: A=g_tH, W=WHf,        out fp32 outf (+bf)
template<int CFG>
__global__ __launch_bounds__(256)
void gemm8(const float* __restrict__ bias, float* __restrict__ outf)
{
    const int m0 = blockIdx.y * 128, n0 = blockIdx.x * 128;
    const __half* Ah_ = (CFG == 0) ? g_aH : (CFG == 1) ? g_bH : (CFG == 2) ? g_kH : g_tH;
    const __half* Wh_ = (CFG == 0) ? g_WHq : (CFG == 1) ? g_WHk
                       : (CFG == 2) ? g_WpB[m0 >> 12] : g_WHf;

    extern __shared__ char smem[];
    const int t = threadIdx.x, lane = t & 31, w = t >> 5;
    const int wm = (w >> 1) * 32, wn = (w & 1) * 64;
    const int g = lane >> 2, tg = lane & 3;

    if (t < 128) ((float*)smem)[t] = bias[n0 + t];

    const uint32_t sbase = s2u(smem) + HDR;

    auto fill = [&](int s, int buf) {
        uint32_t bp = sbase + buf * STAGE_B;
        #pragma unroll
        for (int i = 0; i < 4; i++) {
            const int plane = i >> 1;
            const int p = (i & 1) * 256 + t;
            const int row = p >> 2, sub = (p >> 1) & 1, cc = p & 1;
            const __half* gp = (plane == 0) ? Ah_ : Wh_;
            const int rbase = (plane == 0) ? m0 : n0;
            const void* src = gp + (rbase + row) * DD + s * 32 + sub * 16 + cc * 8;
            uint32_t dst = bp + plane * PLANE_B + sub * SUB_B + row * 48 + cc * 16;
            CP16(dst, src);
        }
    };

    float c[2][8][4] = {};

    fill(0, 0); CP_COMMIT();
    fill(1, 1); CP_COMMIT();

    for (int s = 0; s < NSTG; s++) {
        if (s + 2 < NSTG) fill(s + 2, (s + 2) % 3);
        CP_COMMIT();
        CP_WAIT2();
        __syncthreads();

        const uint32_t* base = (const uint32_t*)(smem + HDR + (s % 3) * STAGE_B);
        #pragma unroll
        for (int kk = 0; kk < 2; kk++) {
            const uint32_t* Awh = base + kk * (SUB_B / 4);
            const uint32_t* Bwh = Awh + PLANE_B / 4;

            uint32_t ah[2][4];
            #pragma unroll
            for (int i = 0; i < 2; i++) {
                int r = wm + i * 16 + g;
                ah[i][0] = Awh[r * 12 + tg];
                ah[i][1] = Awh[(r + 8) * 12 + tg];
                ah[i][2] = Awh[r * 12 + tg + 4];
                ah[i][3] = Awh[(r + 8) * 12 + tg + 4];
            }
            uint32_t bh[8][2];
            #pragma unroll
            for (int j = 0; j < 8; j++) {
                int nb = wn + j * 8 + g;
                bh[j][0] = Bwh[nb * 12 + tg];
                bh[j][1] = Bwh[nb * 12 + tg + 4];
            }
            #pragma unroll
            for (int i = 0; i < 2; i++)
                #pragma unroll
                for (int j = 0; j < 8; j++)
                    MMA_F16(c[i][j], ah[i], bh[j]);
        }
        __syncthreads();
    }

    // Epilogue
    const float* sbias = (const float*)smem;
    #pragma unroll
    for (int i = 0; i < 2; i++) {
        #pragma unroll
        for (int j = 0; j < 8; j++) {
            int rm = m0 + wm + i * 16 + g;
            int cn = n0 + wn + j * 8 + 2 * tg;
            float2 bb = *(const float2*)&sbias[cn - n0];
            float v00 = c[i][j][0] + bb.x, v01 = c[i][j][1] + bb.y;
            float v10 = c[i][j][2] + bb.x, v11 = c[i][j][3] + bb.y;
            if (CFG != 2) {
                float* Cp = (CFG == 0) ? g_Q : (CFG == 1) ? g_K : outf;
                *(float2*)&Cp[rm * DD + cn]       = make_float2(v00, v01);
                *(float2*)&Cp[(rm + 8) * DD + cn] = make_float2(v10, v11);
            } else {
                float2 r0 = *(const float2*)&g_Q[rm * DD + cn];
                float2 r1 = *(const float2*)&g_Q[(rm + 8) * DD + cn];
                v00 += r0.x; v01 += r0.y; v10 += r1.x; v11 += r1.y;
                *(uint32_t*)&g_tH[rm * DD + cn] =
                    pk(__float2half_rn(v00), __float2half_rn(v01));
                *(uint32_t*)&g_tH[(rm + 8) * DD + cn] =
                    pk(__float2half_rn(v10), __float2half_rn(v11));
            }
        }
    }
}

// ---------------- preprocessing --------------------------------------------
// Round both inputs to fp16: grid (IN4/256, 2); y=0 -> a -> g_aH, y=1 -> b.
__global__ __launch_bounds__(256)
void roundin(const float4* __restrict__ a, const float4* __restrict__ b)
{
    const float4* src = blockIdx.y ? b : a;
    __half* dst = blockIdx.y ? g_bH : g_aH;
    int i = blockIdx.x * 256 + threadIdx.x;
    float4 v = src[i];
    ((uint2*)dst)[i] = make_uint2(pk(__float2half_rn(v.x), __float2half_rn(v.y)),
                                  pk(__float2half_rn(v.z), __float2half_rn(v.w)));
}

// Round three weights: grid (W4/256, 3); y selects Wq/Wk/Wf.
// (Device-global destinations selected INSIDE device code — never pass
// __device__ symbols as host-side kernel args; R8 lesson.)
__global__ __launch_bounds__(256)
void roundw3(const float4* __restrict__ Wq, const float4* __restrict__ Wk,
             const float4* __restrict__ Wf)
{
    const float4* src = (blockIdx.y == 0) ? Wq : (blockIdx.y == 1) ? Wk : Wf;
    __half* dst = (blockIdx.y == 0) ? g_WHq : (blockIdx.y == 1) ? g_WHk : g_WHf;
    int i = blockIdx.x * 256 + threadIdx.x;
    float4 v = src[i];
    ((uint2*)dst)[i] = make_uint2(pk(__float2half_rn(v.x), __float2half_rn(v.y)),
                                  pk(__float2half_rn(v.z), __float2half_rn(v.w)));
}

// WpB[b] = fp16(Wp * diag(G[b])) ; grid (DD*DD/1024, BATCH), block 256
__global__ __launch_bounds__(256)
void wpscale(const float4* __restrict__ Wp)
{
    int b = blockIdx.y;
    int i = blockIdx.x * 256 + threadIdx.x;   // float4 index
    int d = (i * 4) & (DD - 1);
    float4 v = Wp[i];
    float4 gv = *(const float4*)&g_G[b * DD + d];
    ((uint2*)g_WpB[b])[i] =
        make_uint2(pk(__float2half_rn(v.x * gv.x), __float2half_rn(v.y * gv.y)),
                   pk(__float2half_rn(v.z * gv.z), __float2half_rn(v.w * gv.w)));
}

// ---------------- l2norm + score + K fp16 ----------------------------------
// rowg < MROWS: Q row -> normalize in place (fp32) + gating score
// else:         K row -> normalize, write fp16 directly (no fp32 store)
__global__ __launch_bounds__(128)
void l2norm_ascore(const float* __restrict__ wg)
{
    int rowg = blockIdx.x;
    bool isQ = rowg < MROWS;
    int r = isQ ? rowg : rowg - MROWS;
    const float* X = isQ ? g_Q : g_K;

    float4 v = *((const float4*)&X[r * DD] + threadIdx.x);
    float s = v.x * v.x + v.y * v.y + v.z * v.z + v.w * v.w;
    #pragma unroll
    for (int off = 16; off > 0; off >>= 1)
        s += __shfl_xor_sync(0xFFFFFFFFu, s, off);

    __shared__ float ws[4];
    int lane = threadIdx.x & 31, wid = threadIdx.x >> 5;
    if (lane == 0) ws[wid] = s;
    __syncthreads();
    float tot = ws[0] + ws[1] + ws[2] + ws[3];
    float inv = 1.0f / fmaxf(sqrtf(tot), 1e-12f);

    v.x *= inv; v.y *= inv; v.z *= inv; v.w *= inv;

    if (isQ) {
        *((float4*)&g_Q[r * DD] + threadIdx.x) = v;
        const float4* wv = reinterpret_cast<const float4*>(wg);
        float4 wq = wv[threadIdx.x];
        float s2 = v.x * wq.x + v.y * wq.y + v.z * wq.z + v.w * wq.w;
        #pragma unroll
        for (int off = 16; off > 0; off >>= 1)
            s2 += __shfl_xor_sync(0xFFFFFFFFu, s2, off);
        __syncthreads();
        if (lane == 0) ws[wid] = s2;
        __syncthreads();
        if (threadIdx.x == 0)
            g_A[r] = (ws[0] + ws[1] + ws[2] + ws[3]) * 4.419417382415922e-2f;
    } else {
        int o = r * DD + threadIdx.x * 4;
        *(uint2*)&g_kH[o] =
            make_uint2(pk(__float2half_rn(v.x), __float2half_rn(v.y)),
                       pk(__float2half_rn(v.z), __float2half_rn(v.w)));
    }
}

__global__ __launch_bounds__(256)
void norma()
{
    int b = blockIdx.x, t = threadIdx.x;
    float s = 0.0f;
    for (int i = t; i < NSEQ; i += 256) {
        float v = g_A[b * NSEQ + i];
        s += v * v;
    }
    #pragma unroll
    for (int off = 16; off > 0; off >>= 1)
        s += __shfl_xor_sync(0xFFFFFFFFu, s, off);
    __shared__ float ws[8];
    int lane = t & 31, wid = t >> 5;
    if (lane == 0) ws[wid] = s;
    __syncthreads();
    if (t == 0) {
        float tot = 0.0f;
        #pragma unroll
        for (int i = 0; i < 8; i++) tot += ws[i];
        g_invA[b] = 1.0f / fmaxf(sqrtf(tot), 1e-12f);
    }
}

__global__ __launch_bounds__(128)
void gpoolp()
{
    int b = blockIdx.y;
    int d = blockIdx.x * 128 + threadIdx.x;
    int ns = blockIdx.z;
    int n0 = ns * (NSEQ / 8);
    float acc = 0.0f;
    #pragma unroll 4
    for (int n = n0; n < n0 + NSEQ / 8; n++)
        acc += g_A[b * NSEQ + n] * g_Q[(b * NSEQ + n) * DD + d];
    g_Gp[ns][b * DD + d] = acc;
}

__global__ __launch_bounds__(128)
void gpoolr()
{
    int i = blockIdx.x * 128 + threadIdx.x;
    int b = i / DD;
    float s = 0.0f;
    #pragma unroll
    for (int p = 0; p < 8; p++) s += g_Gp[p][i];
    g_G[i] = s * g_invA[b];
}

// ---------------------------------------------------------------------------
extern "C" void kernel_launch(void* const* d_in, const int* in_sizes, int n_in,
                              void* d_out, int out_size)
{
    const float* a  = (const float*)d_in[0];
    const float* b  = (const float*)d_in[1];
    const float* Wq = (const float*)d_in[2];
    const float* bq = (const float*)d_in[3];
    const float* Wk = (const float*)d_in[4];
    const float* bk = (const float*)d_in[5];
    const float* wg = (const float*)d_in[6];
    const float* Wp = (const float*)d_in[7];
    const float* bp = (const float*)d_in[8];
    const float* Wf = (const float*)d_in[9];
    const float* bf = (const float*)d_in[10];
    float* out = (float*)d_out;

    cudaFuncSetAttribute(gemm8<0>, cudaFuncAttributeMaxDynamicSharedMemorySize, SMEM_TOTAL);
    cudaFuncSetAttribute(gemm8<1>, cudaFuncAttributeMaxDynamicSharedMemorySize, SMEM_TOTAL);
    cudaFuncSetAttribute(gemm8<2>, cudaFuncAttributeMaxDynamicSharedMemorySize, SMEM_TOTAL);
    cudaFuncSetAttribute(gemm8<3>, cudaFuncAttributeMaxDynamicSharedMemorySize, SMEM_TOTAL);

    const int IN4 = MROWS * DD / 4;   // input float4 count
    const int W4  = DD * DD / 4;      // weight float4 count

    roundin<<<dim3(IN4 / 256, 2), 256>>>((const float4*)a, (const float4*)b);
    roundw3<<<dim3(W4 / 256, 3), 256>>>((const float4*)Wq, (const float4*)Wk,
                                        (const float4*)Wf);

    dim3 gg(4, MROWS / 128);   // (4, 256)

    gemm8<0><<<gg, 256, SMEM_TOTAL>>>(bq, nullptr);   // Q = a@Wq^T + bq
    gemm8<1><<<gg, 256, SMEM_TOTAL>>>(bk, nullptr);   // K = b@Wk^T + bk
    l2norm_ascore<<<2 * MROWS, 128>>>(wg);
    norma<<<BATCH, 256>>>();
    gpoolp<<<dim3(4, BATCH, 8), 128>>>();
    gpoolr<<<32, 128>>>();
    wpscale<<<dim3(W4 / 256, BATCH), 256>>>((const float4*)Wp);
    gemm8<2><<<gg, 256, SMEM_TOTAL>>>(bp, nullptr);   // T = K@(Wp*G)^T+bp+Q (fp16)
    gemm8<3><<<gg, 256, SMEM_TOTAL>>>(bf, out);       // out = T@Wf^T + bf
}